// round 8
// baseline (speedup 1.0000x reference)
#include <cuda_runtime.h>
#include <cuda_bf16.h>
#include <math.h>
#include <stdint.h>

#define B_ 2
#define T_ 2048
#define DIM_ 2048
#define H_ 16
#define HD_ 128
#define BT_ (B_ * T_)

// ---------------------------------------------------------------------------
// Scratch (alloc-free rules: __device__ globals)
// ---------------------------------------------------------------------------
static __device__ float g_q[(size_t)BT_ * DIM_];     // Q after GEMM (pre-RoPE), [B,T,H,HD]
static __device__ float g_attn[(size_t)BT_ * DIM_];  // attention out, [B,T,DIM]
static __device__ __nv_bfloat16 g_qh[(size_t)BT_ * DIM_];   // roped+scaled Q hi/lo
static __device__ __nv_bfloat16 g_ql[(size_t)BT_ * DIM_];
static __device__ __nv_bfloat16 g_kh[(size_t)BT_ * HD_];    // roped K hi/lo [B,T,HD]
static __device__ __nv_bfloat16 g_kl[(size_t)BT_ * HD_];
static __device__ __nv_bfloat16 g_vth[(size_t)BT_ * HD_];   // V^T hi/lo [B,HD,T]
static __device__ __nv_bfloat16 g_vtl[(size_t)BT_ * HD_];
// tf32 (permuted-k) operands for the projection GEMMs
static __device__ uint32_t g_xt[(size_t)BT_ * DIM_];        // x, [M][K] perm
static __device__ uint32_t g_at[(size_t)BT_ * DIM_];        // attn, [M][K] perm
static __device__ uint32_t g_wqt[(size_t)DIM_ * DIM_];      // W^T [N][K] perm
static __device__ uint32_t g_wot[(size_t)DIM_ * DIM_];
static __device__ uint32_t g_wkt[(size_t)HD_ * DIM_];
static __device__ uint32_t g_wvt[(size_t)HD_ * DIM_];

// ---------------------------------------------------------------------------
// helpers
// ---------------------------------------------------------------------------
__device__ __forceinline__ uint32_t f2tf(float x) {
    uint32_t r;
    asm("cvt.rna.tf32.f32 %0, %1;" : "=r"(r) : "f"(x));
    return r;
}
__device__ __forceinline__ uint32_t smem_u32(const void* p) {
    uint32_t a;
    asm("{ .reg .u64 t; cvta.to.shared.u64 t, %1; cvt.u32.u64 %0, t; }" : "=r"(a) : "l"(p));
    return a;
}
__device__ __forceinline__ void mma8(float* c, uint32_t a0, uint32_t a1, uint32_t a2,
                                     uint32_t a3, uint32_t b0, uint32_t b1) {
    asm volatile(
        "mma.sync.aligned.m16n8k8.row.col.f32.tf32.tf32.f32 "
        "{%0,%1,%2,%3},{%4,%5,%6,%7},{%8,%9},{%0,%1,%2,%3};"
        : "+f"(c[0]), "+f"(c[1]), "+f"(c[2]), "+f"(c[3])
        : "r"(a0), "r"(a1), "r"(a2), "r"(a3), "r"(b0), "r"(b1));
}
__device__ __forceinline__ void mmabf(float* c, uint32_t a0, uint32_t a1, uint32_t a2,
                                      uint32_t a3, uint32_t b0, uint32_t b1) {
    asm volatile(
        "mma.sync.aligned.m16n8k16.row.col.f32.bf16.bf16.f32 "
        "{%0,%1,%2,%3},{%4,%5,%6,%7},{%8,%9},{%0,%1,%2,%3};"
        : "+f"(c[0]), "+f"(c[1]), "+f"(c[2]), "+f"(c[3])
        : "r"(a0), "r"(a1), "r"(a2), "r"(a3), "r"(b0), "r"(b1));
}
__device__ __forceinline__ uint32_t pack2bf(float a, float b) {
    __nv_bfloat162 p = __floats2bfloat162_rn(a, b);
    return *(uint32_t*)&p;
}
#define CPA16(d, s) asm volatile("cp.async.cg.shared.global [%0], [%1], 16;" :: "r"(d), "l"(s))
#define CPCOMMIT()  asm volatile("cp.async.commit_group;" ::: "memory")
#define CPWAIT2()   asm volatile("cp.async.wait_group 2;" ::: "memory")

// ---------------------------------------------------------------------------
// Prep: fp32 -> tf32 with k-permutation (slot order k: 0,4,1,5,2,6,3,7 per 8)
// ---------------------------------------------------------------------------
__global__ __launch_bounds__(256) void conv_act(const float* __restrict__ src,
                                                int ssel, int dsel)
{
    const float* s = ssel ? g_attn : src;
    uint32_t* d = dsel ? g_at : g_xt;
    size_t base = ((size_t)blockIdx.x * 256 + threadIdx.x) * 8;
    float4 v0 = *(const float4*)(s + base);
    float4 v1 = *(const float4*)(s + base + 4);
    uint4 o0 = make_uint4(f2tf(v0.x), f2tf(v1.x), f2tf(v0.y), f2tf(v1.y));
    uint4 o1 = make_uint4(f2tf(v0.z), f2tf(v1.z), f2tf(v0.w), f2tf(v1.w));
    *(uint4*)(d + base) = o0;
    *(uint4*)(d + base + 4) = o1;
}

// W [K=2048][N] -> Wt [N][2048] tf32, k-permuted within 8-blocks
__global__ void conv_w(const float* __restrict__ W, int N, int wsel)
{
    __shared__ float t[32][33];
    uint32_t* dst = (wsel == 0) ? g_wqt : (wsel == 1) ? g_wkt : (wsel == 2) ? g_wvt : g_wot;
    int n0 = blockIdx.x * 32, k0 = blockIdx.y * 32;
    int tx = threadIdx.x, ty = threadIdx.y;          // (32, 4)
#pragma unroll
    for (int r = ty; r < 32; r += 4)
        t[r][tx] = W[(size_t)(k0 + r) * N + n0 + tx];
    __syncthreads();
    float f[8];
#pragma unroll
    for (int j = 0; j < 8; j++) f[j] = t[ty * 8 + j][tx];
    uint4 o0 = make_uint4(f2tf(f[0]), f2tf(f[4]), f2tf(f[1]), f2tf(f[5]));
    uint4 o1 = make_uint4(f2tf(f[2]), f2tf(f[6]), f2tf(f[3]), f2tf(f[7]));
    size_t o = (size_t)(n0 + tx) * DIM_ + k0 + ty * 8;
    *(uint4*)&dst[o] = o0;
    *(uint4*)&dst[o + 4] = o1;
}

// ---------------------------------------------------------------------------
// TF32 GEMM, 4-stage cp.async pipeline. C[M,N] = A[M,K=2048] @ B^T ([N][K]).
// 128x128 tile, BK=16, 256 thr (8 warps 2x4, warp 64x32).
// smem: A[4][2 kb][128 m][8 w] (32KB) + B same (32KB) = 64KB dynamic.
// ---------------------------------------------------------------------------
__global__ __launch_bounds__(256, 2) void tgemm(
    int asel, int bsel0, int bsel1,
    float* __restrict__ C0, float* __restrict__ C1, int csel, int N)
{
    extern __shared__ uint32_t sm4[];
    const uint32_t* Ag = asel ? g_at : g_xt;
    int bsel = blockIdx.z ? bsel1 : bsel0;
    const uint32_t* Bg = (bsel == 0) ? g_wqt : (bsel == 1) ? g_wkt
                       : (bsel == 2) ? g_wvt : g_wot;
    float* C = csel ? g_q : (blockIdx.z ? C1 : C0);

    const int K = DIM_;
    int tid = threadIdx.x;
    int bn0 = blockIdx.x * 128, bm0 = blockIdx.y * 128;
    int warp = tid >> 5, lane = tid & 31;
    int wm = (warp & 1) * 64, wn = (warp >> 1) * 32;
    int lr = lane >> 2, lc = lane & 3;
    uint32_t sbase = smem_u32(sm4);

    float acc[4][4][4];
#pragma unroll
    for (int mt = 0; mt < 4; mt++)
#pragma unroll
        for (int nt = 0; nt < 4; nt++)
#pragma unroll
            for (int i = 0; i < 4; i++) acc[mt][nt][i] = 0.f;

    // copy: 512 16B chunks per matrix per stage; each thread 2 A + 2 B
    int c0row = tid >> 2, c0part = tid & 3;
    int c1row = (tid + 256) >> 2, c1part = tid & 3;   // (tid+256)&3 == tid&3
    uint32_t d0 = (uint32_t)(((c0part >> 1) * 1024 + c0row * 8 + (c0part & 1) * 4) * 4);
    uint32_t d1 = (uint32_t)(((c1part >> 1) * 1024 + c1row * 8 + (c1part & 1) * 4) * 4);
    const uint32_t* a0p = Ag + (size_t)(bm0 + c0row) * K + c0part * 4;
    const uint32_t* a1p = Ag + (size_t)(bm0 + c1row) * K + c1part * 4;
    const uint32_t* b0p = Bg + (size_t)(bn0 + c0row) * K + c0part * 4;
    const uint32_t* b1p = Bg + (size_t)(bn0 + c1row) * K + c1part * 4;

#define ISSUE(st, k0) do { \
        uint32_t sb = sbase + (uint32_t)((st) * 8192); \
        CPA16(sb + d0, a0p + (k0)); \
        CPA16(sb + d1, a1p + (k0)); \
        CPA16(sb + 32768 + d0, b0p + (k0)); \
        CPA16(sb + 32768 + d1, b1p + (k0)); \
        CPCOMMIT(); \
    } while (0)

    ISSUE(0, 0);
    ISSUE(1, 16);
    ISSUE(2, 32);

    const int nk = K / 16;   // 128
    for (int t = 0; t < nk; t++) {
        int p = t & 3;
        CPWAIT2();
        __syncthreads();
        if (t + 3 < nk) { int s3 = (t + 3) & 3; int k3 = (t + 3) * 16; ISSUE(s3, k3); }
        else CPCOMMIT();

#pragma unroll
        for (int kb = 0; kb < 2; kb++) {
            int ab = p * 2048 + kb * 1024;
            int bb = 8192 + p * 2048 + kb * 1024;
            uint2 bfr[4];
#pragma unroll
            for (int nt = 0; nt < 4; nt++)
                bfr[nt] = *(uint2*)&sm4[bb + (wn + nt * 8 + lr) * 8 + lc * 2];
#pragma unroll
            for (int mt = 0; mt < 4; mt++) {
                uint2 alo = *(uint2*)&sm4[ab + (wm + mt * 16 + lr) * 8 + lc * 2];
                uint2 ahi = *(uint2*)&sm4[ab + (wm + mt * 16 + lr + 8) * 8 + lc * 2];
#pragma unroll
                for (int nt = 0; nt < 4; nt++)
                    mma8(acc[mt][nt], alo.x, ahi.x, alo.y, ahi.y, bfr[nt].x, bfr[nt].y);
            }
        }
    }

#pragma unroll
    for (int mt = 0; mt < 4; mt++) {
        int row = bm0 + wm + mt * 16 + lr;
#pragma unroll
        for (int nt = 0; nt < 4; nt++) {
            int col = bn0 + wn + nt * 8 + lc * 2;
            *(float2*)&C[(size_t)row * N + col]       = make_float2(acc[mt][nt][0], acc[mt][nt][1]);
            *(float2*)&C[(size_t)(row + 8) * N + col] = make_float2(acc[mt][nt][2], acc[mt][nt][3]);
        }
    }
#undef ISSUE
}

// ---------------------------------------------------------------------------
// RoPE + split kernels (R7, proven)
// ---------------------------------------------------------------------------
__global__ __launch_bounds__(256) void rope_q_split()
{
    int idx = blockIdx.x * 256 + threadIdx.x;
    int j = idx & 63;
    int h = (idx >> 6) & (H_ - 1);
    int t = (idx >> 10) & (T_ - 1);
    int b = idx >> 21;
    const float scale = 0.08838834764831845f;
    float inv = powf(10000.0f, -(float)j * (1.0f / 64.0f));
    float ang = (float)t * inv;
    float sv, cv;
    sincosf(ang, &sv, &cv);
    size_t base = (((size_t)b * T_ + t) * H_ + h) * (size_t)HD_;
    float x1 = g_q[base + j], x2 = g_q[base + j + 64];
    float r1 = (x1 * cv - x2 * sv) * scale;
    float r2 = (x2 * cv + x1 * sv) * scale;
    __nv_bfloat16 h1 = __float2bfloat16(r1);
    __nv_bfloat16 h2 = __float2bfloat16(r2);
    g_qh[base + j] = h1;
    g_qh[base + j + 64] = h2;
    g_ql[base + j] = __float2bfloat16(r1 - __bfloat162float(h1));
    g_ql[base + j + 64] = __float2bfloat16(r2 - __bfloat162float(h2));
}

__global__ __launch_bounds__(256) void rope_k_split(float* __restrict__ kb)
{
    int idx = blockIdx.x * 256 + threadIdx.x;
    int j = idx & 63;
    int t = (idx >> 6) & (T_ - 1);
    int b = idx >> 17;
    float inv = powf(10000.0f, -(float)j * (1.0f / 64.0f));
    float ang = (float)t * inv;
    float sv, cv;
    sincosf(ang, &sv, &cv);
    size_t base = ((size_t)b * T_ + t) * (size_t)HD_;
    float x1 = kb[base + j], x2 = kb[base + j + 64];
    float r1 = x1 * cv - x2 * sv;
    float r2 = x2 * cv + x1 * sv;
    kb[base + j] = r1;
    kb[base + j + 64] = r2;
    __nv_bfloat16 h1 = __float2bfloat16(r1);
    __nv_bfloat16 h2 = __float2bfloat16(r2);
    g_kh[base + j] = h1;
    g_kh[base + j + 64] = h2;
    g_kl[base + j] = __float2bfloat16(r1 - __bfloat162float(h1));
    g_kl[base + j + 64] = __float2bfloat16(r2 - __bfloat162float(h2));
}

__global__ void v_split_t(const float* __restrict__ vb)
{
    __shared__ float tile[32][33];
    int t0 = blockIdx.x * 32, d0 = blockIdx.y * 32, b = blockIdx.z;
    int tx = threadIdx.x, ty = threadIdx.y;
#pragma unroll
    for (int r = ty; r < 32; r += 8)
        tile[r][tx] = vb[((size_t)b * T_ + t0 + r) * HD_ + d0 + tx];
    __syncthreads();
#pragma unroll
    for (int r = ty; r < 32; r += 8) {
        float v = tile[tx][r];
        __nv_bfloat16 hh = __float2bfloat16(v);
        size_t o = ((size_t)b * HD_ + d0 + r) * T_ + t0 + tx;
        g_vth[o] = hh;
        g_vtl[o] = __float2bfloat16(v - __bfloat162float(hh));
    }
}

// ---------------------------------------------------------------------------
// Flash attention, bf16x3, preconverted inputs (R7, proven)
// ---------------------------------------------------------------------------
#define FBQ 64
#define FBKV 64
#define KSTR 136
#define VSTR 72

__global__ __launch_bounds__(128, 2) void flash_bf16()
{
    extern __shared__ __nv_bfloat16 smh[];
    __nv_bfloat16* Kh  = smh;
    __nv_bfloat16* Kl  = Kh + 64 * KSTR;
    __nv_bfloat16* VTh = Kl + 64 * KSTR;
    __nv_bfloat16* VTl = VTh + 128 * VSTR;
    __nv_bfloat16* Ph  = VTl + 128 * VSTR;
    __nv_bfloat16* Pl  = Ph + 64 * VSTR;

    int tid = threadIdx.x;
    int w = tid >> 5, lane = tid & 31;
    int lr = lane >> 2, lc = lane & 3;
    int qb = blockIdx.x;
    int bh = (int)blockIdx.y;
    int b = bh >> 4, h = bh & 15;
    int q0 = qb * FBQ;
    int rb = w * 16;

    uint32_t qfh[8][4], qfl[8][4];
    {
        const __nv_bfloat16* qh = g_qh + (((size_t)b * T_ + q0) * H_ + h) * (size_t)HD_;
        const __nv_bfloat16* ql = g_ql + (((size_t)b * T_ + q0) * H_ + h) * (size_t)HD_;
#pragma unroll
        for (int kk = 0; kk < 8; kk++) {
            int ke = kk * 16;
            qfh[kk][0] = *(const uint32_t*)&qh[(size_t)(rb + lr) * DIM_ + ke + 2 * lc];
            qfh[kk][1] = *(const uint32_t*)&qh[(size_t)(rb + lr + 8) * DIM_ + ke + 2 * lc];
            qfh[kk][2] = *(const uint32_t*)&qh[(size_t)(rb + lr) * DIM_ + ke + 2 * lc + 8];
            qfh[kk][3] = *(const uint32_t*)&qh[(size_t)(rb + lr + 8) * DIM_ + ke + 2 * lc + 8];
            qfl[kk][0] = *(const uint32_t*)&ql[(size_t)(rb + lr) * DIM_ + ke + 2 * lc];
            qfl[kk][1] = *(const uint32_t*)&ql[(size_t)(rb + lr + 8) * DIM_ + ke + 2 * lc];
            qfl[kk][2] = *(const uint32_t*)&ql[(size_t)(rb + lr) * DIM_ + ke + 2 * lc + 8];
            qfl[kk][3] = *(const uint32_t*)&ql[(size_t)(rb + lr + 8) * DIM_ + ke + 2 * lc + 8];
        }
    }

    float m0r = -1e30f, m1r = -1e30f, l0r = 0.f, l1r = 0.f;
    float O[16][4];
#pragma unroll
    for (int i = 0; i < 16; i++)
#pragma unroll
        for (int j = 0; j < 4; j++) O[i][j] = 0.f;

    const __nv_bfloat16* kbh = g_kh + (size_t)b * T_ * HD_;
    const __nv_bfloat16* kbl = g_kl + (size_t)b * T_ * HD_;
    const __nv_bfloat16* vbh = g_vth + (size_t)b * HD_ * T_;
    const __nv_bfloat16* vbl = g_vtl + (size_t)b * HD_ * T_;

    for (int kt = 0; kt <= qb; kt++) {
        int k0 = kt * FBKV;
        __syncthreads();

#pragma unroll
        for (int it = 0; it < 8; it++) {
            int i = tid + it * 128;
            int r = i >> 4, c = (i & 15) * 8;
            size_t ga = (size_t)(k0 + r) * HD_ + c;
            *(uint4*)&Kh[r * KSTR + c] = *(const uint4*)&kbh[ga];
            *(uint4*)&Kl[r * KSTR + c] = *(const uint4*)&kbl[ga];
        }
#pragma unroll
        for (int it = 0; it < 8; it++) {
            int i = tid + it * 128;
            int r = i >> 3, c = (i & 7) * 8;
            size_t ga = (size_t)r * T_ + k0 + c;
            *(uint4*)&VTh[r * VSTR + c] = *(const uint4*)&vbh[ga];
            *(uint4*)&VTl[r * VSTR + c] = *(const uint4*)&vbl[ga];
        }
        __syncthreads();

        float sacc[8][4];
#pragma unroll
        for (int nt = 0; nt < 8; nt++)
#pragma unroll
            for (int j = 0; j < 4; j++) sacc[nt][j] = 0.f;

#pragma unroll
        for (int kk = 0; kk < 8; kk++) {
            int ke = kk * 16;
#pragma unroll
            for (int nt = 0; nt < 8; nt++) {
                int n = nt * 8 + lr;
                uint32_t bh0 = *(uint32_t*)&Kh[n * KSTR + ke + 2 * lc];
                uint32_t bh1 = *(uint32_t*)&Kh[n * KSTR + ke + 2 * lc + 8];
                uint32_t bl0 = *(uint32_t*)&Kl[n * KSTR + ke + 2 * lc];
                uint32_t bl1 = *(uint32_t*)&Kl[n * KSTR + ke + 2 * lc + 8];
                mmabf(sacc[nt], qfh[kk][0], qfh[kk][1], qfh[kk][2], qfh[kk][3], bh0, bh1);
                mmabf(sacc[nt], qfh[kk][0], qfh[kk][1], qfh[kk][2], qfh[kk][3], bl0, bl1);
                mmabf(sacc[nt], qfl[kk][0], qfl[kk][1], qfl[kk][2], qfl[kk][3], bh0, bh1);
            }
        }

        if (kt == qb) {
            int r0g = rb + lr, r1g = r0g + 8;
#pragma unroll
            for (int nt = 0; nt < 8; nt++) {
                int cg = nt * 8 + 2 * lc;
                if (cg > r0g)     sacc[nt][0] = -1e30f;
                if (cg + 1 > r0g) sacc[nt][1] = -1e30f;
                if (cg > r1g)     sacc[nt][2] = -1e30f;
                if (cg + 1 > r1g) sacc[nt][3] = -1e30f;
            }
        }

        float mt0 = -1e30f, mt1 = -1e30f;
#pragma unroll
        for (int nt = 0; nt < 8; nt++) {
            mt0 = fmaxf(mt0, fmaxf(sacc[nt][0], sacc[nt][1]));
            mt1 = fmaxf(mt1, fmaxf(sacc[nt][2], sacc[nt][3]));
        }
        mt0 = fmaxf(mt0, __shfl_xor_sync(0xffffffff, mt0, 1));
        mt0 = fmaxf(mt0, __shfl_xor_sync(0xffffffff, mt0, 2));
        mt1 = fmaxf(mt1, __shfl_xor_sync(0xffffffff, mt1, 1));
        mt1 = fmaxf(mt1, __shfl_xor_sync(0xffffffff, mt1, 2));

        float mn0 = fmaxf(m0r, mt0), mn1 = fmaxf(m1r, mt1);
        float al0f = __expf(m0r - mn0), al1f = __expf(m1r - mn1);
        m0r = mn0; m1r = mn1;

        float rs0 = 0.f, rs1 = 0.f;
#pragma unroll
        for (int nt = 0; nt < 8; nt++) {
            float p0 = __expf(sacc[nt][0] - mn0);
            float p1 = __expf(sacc[nt][1] - mn0);
            float p2 = __expf(sacc[nt][2] - mn1);
            float p3 = __expf(sacc[nt][3] - mn1);
            rs0 += p0 + p1; rs1 += p2 + p3;
            uint32_t h01 = pack2bf(p0, p1);
            uint32_t h23 = pack2bf(p2, p3);
            __nv_bfloat162 hb = *(__nv_bfloat162*)&h01;
            __nv_bfloat162 hb2 = *(__nv_bfloat162*)&h23;
            uint32_t l01 = pack2bf(p0 - __bfloat162float(hb.x), p1 - __bfloat162float(hb.y));
            uint32_t l23 = pack2bf(p2 - __bfloat162float(hb2.x), p3 - __bfloat162float(hb2.y));
            *(uint32_t*)&Ph[(rb + lr) * VSTR + nt * 8 + 2 * lc]     = h01;
            *(uint32_t*)&Ph[(rb + lr + 8) * VSTR + nt * 8 + 2 * lc] = h23;
            *(uint32_t*)&Pl[(rb + lr) * VSTR + nt * 8 + 2 * lc]     = l01;
            *(uint32_t*)&Pl[(rb + lr + 8) * VSTR + nt * 8 + 2 * lc] = l23;
        }
        rs0 += __shfl_xor_sync(0xffffffff, rs0, 1);
        rs0 += __shfl_xor_sync(0xffffffff, rs0, 2);
        rs1 += __shfl_xor_sync(0xffffffff, rs1, 1);
        rs1 += __shfl_xor_sync(0xffffffff, rs1, 2);
        l0r = l0r * al0f + rs0;
        l1r = l1r * al1f + rs1;

#pragma unroll
        for (int nt = 0; nt < 16; nt++) {
            O[nt][0] *= al0f; O[nt][1] *= al0f;
            O[nt][2] *= al1f; O[nt][3] *= al1f;
        }
        __syncwarp();

#pragma unroll
        for (int kk = 0; kk < 4; kk++) {
            int ke = kk * 16;
            uint32_t ah0 = *(uint32_t*)&Ph[(rb + lr) * VSTR + ke + 2 * lc];
            uint32_t ah1 = *(uint32_t*)&Ph[(rb + lr + 8) * VSTR + ke + 2 * lc];
            uint32_t ah2 = *(uint32_t*)&Ph[(rb + lr) * VSTR + ke + 2 * lc + 8];
            uint32_t ah3 = *(uint32_t*)&Ph[(rb + lr + 8) * VSTR + ke + 2 * lc + 8];
            uint32_t al0 = *(uint32_t*)&Pl[(rb + lr) * VSTR + ke + 2 * lc];
            uint32_t al1 = *(uint32_t*)&Pl[(rb + lr + 8) * VSTR + ke + 2 * lc];
            uint32_t al2 = *(uint32_t*)&Pl[(rb + lr) * VSTR + ke + 2 * lc + 8];
            uint32_t al3 = *(uint32_t*)&Pl[(rb + lr + 8) * VSTR + ke + 2 * lc + 8];
#pragma unroll
            for (int nt = 0; nt < 16; nt++) {
                int n = nt * 8 + lr;
                uint32_t bh0 = *(uint32_t*)&VTh[n * VSTR + ke + 2 * lc];
                uint32_t bh1 = *(uint32_t*)&VTh[n * VSTR + ke + 2 * lc + 8];
                uint32_t bl0 = *(uint32_t*)&VTl[n * VSTR + ke + 2 * lc];
                uint32_t bl1 = *(uint32_t*)&VTl[n * VSTR + ke + 2 * lc + 8];
                mmabf(O[nt], ah0, ah1, ah2, ah3, bh0, bh1);
                mmabf(O[nt], ah0, ah1, ah2, ah3, bl0, bl1);
                mmabf(O[nt], al0, al1, al2, al3, bh0, bh1);
            }
        }
    }

    float inv0 = 1.f / l0r, inv1 = 1.f / l1r;
    float* ob = g_attn + (((size_t)b * T_ + q0) * H_ + h) * (size_t)HD_;
#pragma unroll
    for (int nt = 0; nt < 16; nt++) {
        int col = nt * 8 + 2 * lc;
        *(float2*)&ob[(size_t)(rb + lr) * DIM_ + col] =
            make_float2(O[nt][0] * inv0, O[nt][1] * inv0);
        *(float2*)&ob[(size_t)(rb + lr + 8) * DIM_ + col] =
            make_float2(O[nt][2] * inv1, O[nt][3] * inv1);
    }
}

static const int FLASH_SMEM = (2 * 64 * KSTR + 2 * 128 * VSTR + 2 * 64 * VSTR) * 2;
static const int GEMM_SMEM = 65536;

// ---------------------------------------------------------------------------
extern "C" void kernel_launch(void* const* d_in, const int* in_sizes, int n_in,
                              void* d_out, int out_size)
{
    const float* x  = (const float*)d_in[0];
    const float* Wq = (const float*)d_in[1];
    const float* Wk = (const float*)d_in[2];
    const float* Wv = (const float*)d_in[3];
    const float* Wo = (const float*)d_in[4];

    float* out = (float*)d_out;                       // [B,T,DIM]
    float* pk  = out + (size_t)BT_ * DIM_;            // present_k [B,1,T,HD]
    float* pv  = pk + (size_t)BT_ * HD_;              // present_v [B,1,T,HD]

    cudaFuncSetAttribute(flash_bf16, cudaFuncAttributeMaxDynamicSharedMemorySize, FLASH_SMEM);
    cudaFuncSetAttribute(tgemm, cudaFuncAttributeMaxDynamicSharedMemorySize, GEMM_SMEM);

    // prep: tf32 conversions
    conv_act<<<(BT_ * DIM_ / 8) / 256, 256>>>(x, 0, 0);
    conv_w<<<dim3(DIM_ / 32, DIM_ / 32), dim3(32, 4)>>>(Wq, DIM_, 0);
    conv_w<<<dim3(HD_ / 32, DIM_ / 32), dim3(32, 4)>>>(Wk, HD_, 1);
    conv_w<<<dim3(HD_ / 32, DIM_ / 32), dim3(32, 4)>>>(Wv, HD_, 2);
    conv_w<<<dim3(DIM_ / 32, DIM_ / 32), dim3(32, 4)>>>(Wo, DIM_, 3);

    // Q = x @ Wq -> g_q ; K,V fused -> pk, pv
    tgemm<<<dim3(DIM_ / 128, BT_ / 128, 1), 256, GEMM_SMEM>>>(0, 0, 0, nullptr, nullptr, 1, DIM_);
    tgemm<<<dim3(1, BT_ / 128, 2), 256, GEMM_SMEM>>>(0, 1, 2, pk, pv, 0, HD_);

    // RoPE + bf16 hi/lo pre-split (+ V transpose)
    rope_q_split<<<(BT_ * H_ * 64) / 256, 256>>>();
    rope_k_split<<<(BT_ * 64) / 256, 256>>>(pk);
    v_split_t<<<dim3(T_ / 32, HD_ / 32, B_), dim3(32, 8)>>>(pv);

    // Attention -> g_attn
    flash_bf16<<<dim3(T_ / FBQ, B_ * H_), 128, FLASH_SMEM>>>();

    // out = attn @ Wo
    conv_act<<<(BT_ * DIM_ / 8) / 256, 256>>>(nullptr, 1, 1);
    tgemm<<<dim3(DIM_ / 128, BT_ / 128, 1), 256, GEMM_SMEM>>>(1, 3, 3, out, out, 0, DIM_);
}

// round 9
// speedup vs baseline: 1.6175x; 1.6175x over previous
#include <cuda_runtime.h>
#include <cuda_bf16.h>
#include <cuda_fp16.h>
#include <math.h>
#include <stdint.h>

#define B_ 2
#define T_ 2048
#define DIM_ 2048
#define H_ 16
#define HD_ 128
#define BT_ (B_ * T_)

// ---------------------------------------------------------------------------
// Scratch (alloc-free rules: __device__ globals)
// ---------------------------------------------------------------------------
static __device__ float g_q[(size_t)BT_ * DIM_];     // Q after GEMM (pre-RoPE)
static __device__ float g_attn[(size_t)BT_ * DIM_];  // attention out
static __device__ __half g_qh[(size_t)BT_ * DIM_];   // roped+scaled Q (fp16)
static __device__ __half g_kh[(size_t)BT_ * HD_];    // roped K (fp16) [B,T,HD]
static __device__ __nv_bfloat16 g_vth[(size_t)BT_ * HD_];   // V^T hi/lo [B,HD,T]
static __device__ __nv_bfloat16 g_vtl[(size_t)BT_ * HD_];
// fp16 k-pair-permuted operands for projection GEMMs (uint32 = 2 halfs)
static __device__ uint32_t g_xt[(size_t)BT_ * DIM_ / 2];
static __device__ uint32_t g_at[(size_t)BT_ * DIM_ / 2];
static __device__ uint32_t g_wqt[(size_t)DIM_ * DIM_ / 2];  // W^T [N][K]
static __device__ uint32_t g_wot[(size_t)DIM_ * DIM_ / 2];
static __device__ uint32_t g_wkt[(size_t)HD_ * DIM_ / 2];
static __device__ uint32_t g_wvt[(size_t)HD_ * DIM_ / 2];

// ---------------------------------------------------------------------------
// helpers
// ---------------------------------------------------------------------------
__device__ __forceinline__ uint32_t smem_u32(const void* p) {
    uint32_t a;
    asm("{ .reg .u64 t; cvta.to.shared.u64 t, %1; cvt.u32.u64 %0, t; }" : "=r"(a) : "l"(p));
    return a;
}
__device__ __forceinline__ void mmafp(float* c, uint32_t a0, uint32_t a1, uint32_t a2,
                                      uint32_t a3, uint32_t b0, uint32_t b1) {
    asm volatile(
        "mma.sync.aligned.m16n8k16.row.col.f32.f16.f16.f32 "
        "{%0,%1,%2,%3},{%4,%5,%6,%7},{%8,%9},{%0,%1,%2,%3};"
        : "+f"(c[0]), "+f"(c[1]), "+f"(c[2]), "+f"(c[3])
        : "r"(a0), "r"(a1), "r"(a2), "r"(a3), "r"(b0), "r"(b1));
}
__device__ __forceinline__ void mmabf(float* c, uint32_t a0, uint32_t a1, uint32_t a2,
                                      uint32_t a3, uint32_t b0, uint32_t b1) {
    asm volatile(
        "mma.sync.aligned.m16n8k16.row.col.f32.bf16.bf16.f32 "
        "{%0,%1,%2,%3},{%4,%5,%6,%7},{%8,%9},{%0,%1,%2,%3};"
        : "+f"(c[0]), "+f"(c[1]), "+f"(c[2]), "+f"(c[3])
        : "r"(a0), "r"(a1), "r"(a2), "r"(a3), "r"(b0), "r"(b1));
}
__device__ __forceinline__ uint32_t pack2bf(float a, float b) {
    __nv_bfloat162 p = __floats2bfloat162_rn(a, b);
    return *(uint32_t*)&p;
}
__device__ __forceinline__ uint32_t pack2h(float a, float b) {
    __half2 p = __floats2half2_rn(a, b);
    return *(uint32_t*)&p;
}
#define CPA16(d, s) asm volatile("cp.async.cg.shared.global [%0], [%1], 16;" :: "r"(d), "l"(s))
#define CPCOMMIT()  asm volatile("cp.async.commit_group;" ::: "memory")
#define CPWAIT2()   asm volatile("cp.async.wait_group 2;" ::: "memory")

// ---------------------------------------------------------------------------
// Prep: fp32 -> fp16, k-pair permutation within 16-blocks:
// word w of a block: w=2g -> halfs (k=2g,2g+1); w=2g+1 -> (2g+8, 2g+9)
// ---------------------------------------------------------------------------
__global__ __launch_bounds__(256) void conv_act(const float* __restrict__ src,
                                                int ssel, int dsel)
{
    const float* s = ssel ? g_attn : src;
    uint32_t* d = dsel ? g_at : g_xt;
    size_t i = (size_t)blockIdx.x * 256 + threadIdx.x;   // one 16-float block
    size_t base = i * 16;
    float f[16];
#pragma unroll
    for (int j = 0; j < 16; j += 4) *(float4*)(f + j) = *(const float4*)(s + base + j);
    uint32_t w[8];
#pragma unroll
    for (int g = 0; g < 4; g++) {
        w[2 * g]     = pack2h(f[2 * g], f[2 * g + 1]);
        w[2 * g + 1] = pack2h(f[2 * g + 8], f[2 * g + 9]);
    }
    *(uint4*)(d + i * 8)     = make_uint4(w[0], w[1], w[2], w[3]);
    *(uint4*)(d + i * 8 + 4) = make_uint4(w[4], w[5], w[6], w[7]);
}

// W [K=2048][N] -> Wt [N][K] fp16, k-pair-permuted
__global__ void conv_w(const float* __restrict__ W, int N, int wsel)
{
    __shared__ float t[32][33];
    uint32_t* dst = (wsel == 0) ? g_wqt : (wsel == 1) ? g_wkt : (wsel == 2) ? g_wvt : g_wot;
    int n0 = blockIdx.x * 32, k0 = blockIdx.y * 32;
    int tx = threadIdx.x, ty = threadIdx.y;          // (32, 2)
#pragma unroll
    for (int r = ty; r < 32; r += 2)
        t[r][tx] = W[(size_t)(k0 + r) * N + n0 + tx];
    __syncthreads();
    float f[16];
#pragma unroll
    for (int j = 0; j < 16; j++) f[j] = t[ty * 16 + j][tx];
    uint32_t w[8];
#pragma unroll
    for (int g = 0; g < 4; g++) {
        w[2 * g]     = pack2h(f[2 * g], f[2 * g + 1]);
        w[2 * g + 1] = pack2h(f[2 * g + 8], f[2 * g + 9]);
    }
    size_t o = (size_t)(n0 + tx) * (DIM_ / 2) + (size_t)(k0 + ty * 16) / 2;
    *(uint4*)(dst + o)     = make_uint4(w[0], w[1], w[2], w[3]);
    *(uint4*)(dst + o + 4) = make_uint4(w[4], w[5], w[6], w[7]);
}

// ---------------------------------------------------------------------------
// FP16 GEMM, 4-stage cp.async pipeline. C[M,N] = A[M,K=2048] @ B^T ([N][K]).
// 128x128 tile, stage = k32, 256 thr (8 warps 2x4, warp 64x32).
// smem: A[4][2 kb16][128 m][8 w] 32KB + B same 32KB.
// ---------------------------------------------------------------------------
__global__ __launch_bounds__(256, 2) void hgemm(
    int asel, int bsel0, int bsel1,
    float* __restrict__ C0, float* __restrict__ C1, int csel, int N)
{
    extern __shared__ uint32_t sm4[];
    const uint32_t* Ag = asel ? g_at : g_xt;
    int bsel = blockIdx.z ? bsel1 : bsel0;
    const uint32_t* Bg = (bsel == 0) ? g_wqt : (bsel == 1) ? g_wkt
                       : (bsel == 2) ? g_wvt : g_wot;
    float* C = csel ? g_q : (blockIdx.z ? C1 : C0);

    const int KW = DIM_ / 2;   // uint32 words per row
    int tid = threadIdx.x;
    int bn0 = blockIdx.x * 128, bm0 = blockIdx.y * 128;
    int warp = tid >> 5, lane = tid & 31;
    int wm = (warp & 1) * 64, wn = (warp >> 1) * 32;
    int lr = lane >> 2, lc = lane & 3;
    uint32_t sbase = smem_u32(sm4);

    float acc[4][4][4];
#pragma unroll
    for (int mt = 0; mt < 4; mt++)
#pragma unroll
        for (int nt = 0; nt < 4; nt++)
#pragma unroll
            for (int i = 0; i < 4; i++) acc[mt][nt][i] = 0.f;

    // copy geometry: per stage per matrix 512 16B chunks; each thread 2 A + 2 B
    int c0row = tid >> 2, c0part = tid & 3;
    int c1row = c0row + 64;
    uint32_t d0 = (uint32_t)((((c0part >> 1) * 1024) + c0row * 8 + (c0part & 1) * 4) * 4);
    uint32_t d1 = (uint32_t)((((c0part >> 1) * 1024) + c1row * 8 + (c0part & 1) * 4) * 4);
    int koff = (c0part >> 1) * 8 + (c0part & 1) * 4;
    const uint32_t* a0p = Ag + (size_t)(bm0 + c0row) * KW + koff;
    const uint32_t* a1p = Ag + (size_t)(bm0 + c1row) * KW + koff;
    const uint32_t* b0p = Bg + (size_t)(bn0 + c0row) * KW + koff;
    const uint32_t* b1p = Bg + (size_t)(bn0 + c1row) * KW + koff;

#define ISSUE(st, k0) do { \
        uint32_t sb = sbase + (uint32_t)((st) * 8192); \
        CPA16(sb + d0, a0p + (k0)); \
        CPA16(sb + d1, a1p + (k0)); \
        CPA16(sb + 32768 + d0, b0p + (k0)); \
        CPA16(sb + 32768 + d1, b1p + (k0)); \
        CPCOMMIT(); \
    } while (0)

    ISSUE(0, 0);
    ISSUE(1, 16);
    ISSUE(2, 32);

    const int nk = 64;   // k32 per iter
    for (int t = 0; t < nk; t++) {
        int p = t & 3;
        CPWAIT2();
        __syncthreads();
        if (t + 3 < nk) { ISSUE((t + 3) & 3, (t + 3) * 16); }
        else CPCOMMIT();

#pragma unroll
        for (int kb = 0; kb < 2; kb++) {
            int ab = p * 2048 + kb * 1024;
            int bb = 8192 + p * 2048 + kb * 1024;
            uint2 bfr[4];
#pragma unroll
            for (int nt = 0; nt < 4; nt++)
                bfr[nt] = *(uint2*)&sm4[bb + (wn + nt * 8 + lr) * 8 + lc * 2];
#pragma unroll
            for (int mt = 0; mt < 4; mt++) {
                uint2 alo = *(uint2*)&sm4[ab + (wm + mt * 16 + lr) * 8 + lc * 2];
                uint2 ahi = *(uint2*)&sm4[ab + (wm + mt * 16 + lr + 8) * 8 + lc * 2];
#pragma unroll
                for (int nt = 0; nt < 4; nt++)
                    mmafp(acc[mt][nt], alo.x, ahi.x, alo.y, ahi.y, bfr[nt].x, bfr[nt].y);
            }
        }
    }

#pragma unroll
    for (int mt = 0; mt < 4; mt++) {
        int row = bm0 + wm + mt * 16 + lr;
#pragma unroll
        for (int nt = 0; nt < 4; nt++) {
            int col = bn0 + wn + nt * 8 + lc * 2;
            *(float2*)&C[(size_t)row * N + col]       = make_float2(acc[mt][nt][0], acc[mt][nt][1]);
            *(float2*)&C[(size_t)(row + 8) * N + col] = make_float2(acc[mt][nt][2], acc[mt][nt][3]);
        }
    }
#undef ISSUE
}

// ---------------------------------------------------------------------------
// RoPE + conversion kernels
// ---------------------------------------------------------------------------
__global__ __launch_bounds__(256) void rope_q_split()
{
    int idx = blockIdx.x * 256 + threadIdx.x;
    int j = idx & 63;
    int h = (idx >> 6) & (H_ - 1);
    int t = (idx >> 10) & (T_ - 1);
    int b = idx >> 21;
    const float scale = 0.08838834764831845f;
    float inv = powf(10000.0f, -(float)j * (1.0f / 64.0f));
    float ang = (float)t * inv;
    float sv, cv;
    sincosf(ang, &sv, &cv);
    size_t base = (((size_t)b * T_ + t) * H_ + h) * (size_t)HD_;
    float x1 = g_q[base + j], x2 = g_q[base + j + 64];
    g_qh[base + j]      = __float2half((x1 * cv - x2 * sv) * scale);
    g_qh[base + j + 64] = __float2half((x2 * cv + x1 * sv) * scale);
}

__global__ __launch_bounds__(256) void rope_k_split(float* __restrict__ kb)
{
    int idx = blockIdx.x * 256 + threadIdx.x;
    int j = idx & 63;
    int t = (idx >> 6) & (T_ - 1);
    int b = idx >> 17;
    float inv = powf(10000.0f, -(float)j * (1.0f / 64.0f));
    float ang = (float)t * inv;
    float sv, cv;
    sincosf(ang, &sv, &cv);
    size_t base = ((size_t)b * T_ + t) * (size_t)HD_;
    float x1 = kb[base + j], x2 = kb[base + j + 64];
    float r1 = x1 * cv - x2 * sv;
    float r2 = x2 * cv + x1 * sv;
    kb[base + j] = r1;              // present_k output (fp32)
    kb[base + j + 64] = r2;
    g_kh[base + j]      = __float2half(r1);
    g_kh[base + j + 64] = __float2half(r2);
}

__global__ void v_split_t(const float* __restrict__ vb)
{
    __shared__ float tile[32][33];
    int t0 = blockIdx.x * 32, d0 = blockIdx.y * 32, b = blockIdx.z;
    int tx = threadIdx.x, ty = threadIdx.y;
#pragma unroll
    for (int r = ty; r < 32; r += 8)
        tile[r][tx] = vb[((size_t)b * T_ + t0 + r) * HD_ + d0 + tx];
    __syncthreads();
#pragma unroll
    for (int r = ty; r < 32; r += 8) {
        float v = tile[tx][r];
        __nv_bfloat16 hh = __float2bfloat16(v);
        size_t o = ((size_t)b * HD_ + d0 + r) * T_ + t0 + tx;
        g_vth[o] = hh;
        g_vtl[o] = __float2bfloat16(v - __bfloat162float(hh));
    }
}

// ---------------------------------------------------------------------------
// Flash attention: S = fp16 x1 mma, PV = bf16x3. BQ=BKV=64, 128 thr, 2 CTA/SM.
// ---------------------------------------------------------------------------
#define FBQ 64
#define FBKV 64
#define KSTR 136
#define VSTR 72

__global__ __launch_bounds__(128, 2) void flash_mixed()
{
    extern __shared__ __half smh[];
    __half* Kh = smh;                                        // [64][KSTR] fp16
    __nv_bfloat16* VTh = (__nv_bfloat16*)(Kh + 64 * KSTR);   // [128][VSTR]
    __nv_bfloat16* VTl = VTh + 128 * VSTR;
    __nv_bfloat16* Ph  = VTl + 128 * VSTR;                   // [64][VSTR]
    __nv_bfloat16* Pl  = Ph + 64 * VSTR;

    int tid = threadIdx.x;
    int w = tid >> 5, lane = tid & 31;
    int lr = lane >> 2, lc = lane & 3;
    int qb = blockIdx.x;
    int bh = (int)blockIdx.y;
    int b = bh >> 4, h = bh & 15;
    int q0 = qb * FBQ;
    int rb = w * 16;

    // Q fragments (fp16) in registers
    uint32_t qf[8][4];
    {
        const __half* qh = g_qh + (((size_t)b * T_ + q0) * H_ + h) * (size_t)HD_;
#pragma unroll
        for (int kk = 0; kk < 8; kk++) {
            int ke = kk * 16;
            qf[kk][0] = *(const uint32_t*)&qh[(size_t)(rb + lr) * DIM_ + ke + 2 * lc];
            qf[kk][1] = *(const uint32_t*)&qh[(size_t)(rb + lr + 8) * DIM_ + ke + 2 * lc];
            qf[kk][2] = *(const uint32_t*)&qh[(size_t)(rb + lr) * DIM_ + ke + 2 * lc + 8];
            qf[kk][3] = *(const uint32_t*)&qh[(size_t)(rb + lr + 8) * DIM_ + ke + 2 * lc + 8];
        }
    }

    float m0r = -1e30f, m1r = -1e30f, l0r = 0.f, l1r = 0.f;
    float O[16][4];
#pragma unroll
    for (int i = 0; i < 16; i++)
#pragma unroll
        for (int j = 0; j < 4; j++) O[i][j] = 0.f;

    const __half* kbh = g_kh + (size_t)b * T_ * HD_;
    const __nv_bfloat16* vbh = g_vth + (size_t)b * HD_ * T_;
    const __nv_bfloat16* vbl = g_vtl + (size_t)b * HD_ * T_;

    for (int kt = 0; kt <= qb; kt++) {
        int k0 = kt * FBKV;
        __syncthreads();

        // K tile: 64 x 128 fp16
#pragma unroll
        for (int it = 0; it < 8; it++) {
            int i = tid + it * 128;
            int r = i >> 4, c = (i & 15) * 8;
            *(uint4*)&Kh[r * KSTR + c] = *(const uint4*)&kbh[(size_t)(k0 + r) * HD_ + c];
        }
        // V^T tile: 128 x 64 bf16 hi+lo
#pragma unroll
        for (int it = 0; it < 8; it++) {
            int i = tid + it * 128;
            int r = i >> 3, c = (i & 7) * 8;
            size_t ga = (size_t)r * T_ + k0 + c;
            *(uint4*)&VTh[r * VSTR + c] = *(const uint4*)&vbh[ga];
            *(uint4*)&VTl[r * VSTR + c] = *(const uint4*)&vbl[ga];
        }
        __syncthreads();

        // S = Q @ K^T (fp16 x1)
        float sacc[8][4];
#pragma unroll
        for (int nt = 0; nt < 8; nt++)
#pragma unroll
            for (int j = 0; j < 4; j++) sacc[nt][j] = 0.f;

#pragma unroll
        for (int kk = 0; kk < 8; kk++) {
            int ke = kk * 16;
#pragma unroll
            for (int nt = 0; nt < 8; nt++) {
                int n = nt * 8 + lr;
                uint32_t b0 = *(uint32_t*)&Kh[n * KSTR + ke + 2 * lc];
                uint32_t b1 = *(uint32_t*)&Kh[n * KSTR + ke + 2 * lc + 8];
                mmafp(sacc[nt], qf[kk][0], qf[kk][1], qf[kk][2], qf[kk][3], b0, b1);
            }
        }

        if (kt == qb) {
            int r0g = rb + lr, r1g = r0g + 8;
#pragma unroll
            for (int nt = 0; nt < 8; nt++) {
                int cg = nt * 8 + 2 * lc;
                if (cg > r0g)     sacc[nt][0] = -1e30f;
                if (cg + 1 > r0g) sacc[nt][1] = -1e30f;
                if (cg > r1g)     sacc[nt][2] = -1e30f;
                if (cg + 1 > r1g) sacc[nt][3] = -1e30f;
            }
        }

        float mt0 = -1e30f, mt1 = -1e30f;
#pragma unroll
        for (int nt = 0; nt < 8; nt++) {
            mt0 = fmaxf(mt0, fmaxf(sacc[nt][0], sacc[nt][1]));
            mt1 = fmaxf(mt1, fmaxf(sacc[nt][2], sacc[nt][3]));
        }
        mt0 = fmaxf(mt0, __shfl_xor_sync(0xffffffff, mt0, 1));
        mt0 = fmaxf(mt0, __shfl_xor_sync(0xffffffff, mt0, 2));
        mt1 = fmaxf(mt1, __shfl_xor_sync(0xffffffff, mt1, 1));
        mt1 = fmaxf(mt1, __shfl_xor_sync(0xffffffff, mt1, 2));

        float mn0 = fmaxf(m0r, mt0), mn1 = fmaxf(m1r, mt1);
        float al0f = __expf(m0r - mn0), al1f = __expf(m1r - mn1);
        m0r = mn0; m1r = mn1;

        float rs0 = 0.f, rs1 = 0.f;
#pragma unroll
        for (int nt = 0; nt < 8; nt++) {
            float p0 = __expf(sacc[nt][0] - mn0);
            float p1 = __expf(sacc[nt][1] - mn0);
            float p2 = __expf(sacc[nt][2] - mn1);
            float p3 = __expf(sacc[nt][3] - mn1);
            rs0 += p0 + p1; rs1 += p2 + p3;
            uint32_t h01 = pack2bf(p0, p1);
            uint32_t h23 = pack2bf(p2, p3);
            __nv_bfloat162 hb = *(__nv_bfloat162*)&h01;
            __nv_bfloat162 hb2 = *(__nv_bfloat162*)&h23;
            uint32_t l01 = pack2bf(p0 - __bfloat162float(hb.x), p1 - __bfloat162float(hb.y));
            uint32_t l23 = pack2bf(p2 - __bfloat162float(hb2.x), p3 - __bfloat162float(hb2.y));
            *(uint32_t*)&Ph[(rb + lr) * VSTR + nt * 8 + 2 * lc]     = h01;
            *(uint32_t*)&Ph[(rb + lr + 8) * VSTR + nt * 8 + 2 * lc] = h23;
            *(uint32_t*)&Pl[(rb + lr) * VSTR + nt * 8 + 2 * lc]     = l01;
            *(uint32_t*)&Pl[(rb + lr + 8) * VSTR + nt * 8 + 2 * lc] = l23;
        }
        rs0 += __shfl_xor_sync(0xffffffff, rs0, 1);
        rs0 += __shfl_xor_sync(0xffffffff, rs0, 2);
        rs1 += __shfl_xor_sync(0xffffffff, rs1, 1);
        rs1 += __shfl_xor_sync(0xffffffff, rs1, 2);
        l0r = l0r * al0f + rs0;
        l1r = l1r * al1f + rs1;

#pragma unroll
        for (int nt = 0; nt < 16; nt++) {
            O[nt][0] *= al0f; O[nt][1] *= al0f;
            O[nt][2] *= al1f; O[nt][3] *= al1f;
        }
        __syncwarp();

        // O += P @ V (bf16x3)
#pragma unroll
        for (int kk = 0; kk < 4; kk++) {
            int ke = kk * 16;
            uint32_t ah0 = *(uint32_t*)&Ph[(rb + lr) * VSTR + ke + 2 * lc];
            uint32_t ah1 = *(uint32_t*)&Ph[(rb + lr + 8) * VSTR + ke + 2 * lc];
            uint32_t ah2 = *(uint32_t*)&Ph[(rb + lr) * VSTR + ke + 2 * lc + 8];
            uint32_t ah3 = *(uint32_t*)&Ph[(rb + lr + 8) * VSTR + ke + 2 * lc + 8];
            uint32_t al0 = *(uint32_t*)&Pl[(rb + lr) * VSTR + ke + 2 * lc];
            uint32_t al1 = *(uint32_t*)&Pl[(rb + lr + 8) * VSTR + ke + 2 * lc];
            uint32_t al2 = *(uint32_t*)&Pl[(rb + lr) * VSTR + ke + 2 * lc + 8];
            uint32_t al3 = *(uint32_t*)&Pl[(rb + lr + 8) * VSTR + ke + 2 * lc + 8];
#pragma unroll
            for (int nt = 0; nt < 16; nt++) {
                int n = nt * 8 + lr;
                uint32_t bh0 = *(uint32_t*)&VTh[n * VSTR + ke + 2 * lc];
                uint32_t bh1 = *(uint32_t*)&VTh[n * VSTR + ke + 2 * lc + 8];
                uint32_t bl0 = *(uint32_t*)&VTl[n * VSTR + ke + 2 * lc];
                uint32_t bl1 = *(uint32_t*)&VTl[n * VSTR + ke + 2 * lc + 8];
                mmabf(O[nt], ah0, ah1, ah2, ah3, bh0, bh1);
                mmabf(O[nt], ah0, ah1, ah2, ah3, bl0, bl1);
                mmabf(O[nt], al0, al1, al2, al3, bh0, bh1);
            }
        }
    }

    float inv0 = 1.f / l0r, inv1 = 1.f / l1r;
    float* ob = g_attn + (((size_t)b * T_ + q0) * H_ + h) * (size_t)HD_;
#pragma unroll
    for (int nt = 0; nt < 16; nt++) {
        int col = nt * 8 + 2 * lc;
        *(float2*)&ob[(size_t)(rb + lr) * DIM_ + col] =
            make_float2(O[nt][0] * inv0, O[nt][1] * inv0);
        *(float2*)&ob[(size_t)(rb + lr + 8) * DIM_ + col] =
            make_float2(O[nt][2] * inv1, O[nt][3] * inv1);
    }
}

static const int FLASH_SMEM = (64 * KSTR + 2 * 128 * VSTR + 2 * 64 * VSTR) * 2;
static const int GEMM_SMEM = 65536;

// ---------------------------------------------------------------------------
extern "C" void kernel_launch(void* const* d_in, const int* in_sizes, int n_in,
                              void* d_out, int out_size)
{
    const float* x  = (const float*)d_in[0];
    const float* Wq = (const float*)d_in[1];
    const float* Wk = (const float*)d_in[2];
    const float* Wv = (const float*)d_in[3];
    const float* Wo = (const float*)d_in[4];

    float* out = (float*)d_out;                       // [B,T,DIM]
    float* pk  = out + (size_t)BT_ * DIM_;            // present_k [B,1,T,HD]
    float* pv  = pk + (size_t)BT_ * HD_;              // present_v [B,1,T,HD]

    cudaFuncSetAttribute(flash_mixed, cudaFuncAttributeMaxDynamicSharedMemorySize, FLASH_SMEM);
    cudaFuncSetAttribute(hgemm, cudaFuncAttributeMaxDynamicSharedMemorySize, GEMM_SMEM);

    // prep: fp16 conversions
    conv_act<<<(BT_ * DIM_ / 16) / 256, 256>>>(x, 0, 0);
    conv_w<<<dim3(DIM_ / 32, DIM_ / 32), dim3(32, 2)>>>(Wq, DIM_, 0);
    conv_w<<<dim3(HD_ / 32, DIM_ / 32), dim3(32, 2)>>>(Wk, HD_, 1);
    conv_w<<<dim3(HD_ / 32, DIM_ / 32), dim3(32, 2)>>>(Wv, HD_, 2);
    conv_w<<<dim3(DIM_ / 32, DIM_ / 32), dim3(32, 2)>>>(Wo, DIM_, 3);

    // Q = x @ Wq -> g_q ; K,V fused -> pk, pv
    hgemm<<<dim3(DIM_ / 128, BT_ / 128, 1), 256, GEMM_SMEM>>>(0, 0, 0, nullptr, nullptr, 1, DIM_);
    hgemm<<<dim3(1, BT_ / 128, 2), 256, GEMM_SMEM>>>(0, 1, 2, pk, pv, 0, HD_);

    // RoPE + fp16 conversion (+ V transpose/split)
    rope_q_split<<<(BT_ * H_ * 64) / 256, 256>>>();
    rope_k_split<<<(BT_ * 64) / 256, 256>>>(pk);
    v_split_t<<<dim3(T_ / 32, HD_ / 32, B_), dim3(32, 8)>>>(pv);

    // Attention -> g_attn
    flash_mixed<<<dim3(T_ / FBQ, B_ * H_), 128, FLASH_SMEM>>>();

    // out = attn @ Wo
    conv_act<<<(BT_ * DIM_ / 16) / 256, 256>>>(nullptr, 1, 1);
    hgemm<<<dim3(DIM_ / 128, BT_ / 128, 1), 256, GEMM_SMEM>>>(1, 3, 3, out, out, 0, DIM_);
}

// round 10
// speedup vs baseline: 1.9141x; 1.1834x over previous
#include <cuda_runtime.h>
#include <cuda_bf16.h>
#include <cuda_fp16.h>
#include <math.h>
#include <stdint.h>

#define B_ 2
#define T_ 2048
#define DIM_ 2048
#define H_ 16
#define HD_ 128
#define BT_ (B_ * T_)

// ---------------------------------------------------------------------------
// Scratch (alloc-free rules: __device__ globals)
// ---------------------------------------------------------------------------
static __device__ float g_q[(size_t)BT_ * DIM_];     // Q after GEMM (pre-RoPE)
static __device__ __half g_qh[(size_t)BT_ * DIM_];   // roped+scaled Q (fp16)
static __device__ __half g_kh[(size_t)BT_ * HD_];    // roped K (fp16) [B,T,HD]
static __device__ __half g_vth[(size_t)BT_ * HD_];   // V^T hi/lo fp16 [B,HD,T]
static __device__ __half g_vtl[(size_t)BT_ * HD_];
// fp16 k-pair-permuted operands for projection GEMMs (uint32 = 2 halfs)
static __device__ uint32_t g_xt[(size_t)BT_ * DIM_ / 2];
static __device__ uint32_t g_at[(size_t)BT_ * DIM_ / 2];    // attn out (written by flash)
static __device__ uint32_t g_wqt[(size_t)DIM_ * DIM_ / 2];  // W^T [N][K]
static __device__ uint32_t g_wot[(size_t)DIM_ * DIM_ / 2];
static __device__ uint32_t g_wkt[(size_t)HD_ * DIM_ / 2];
static __device__ uint32_t g_wvt[(size_t)HD_ * DIM_ / 2];

// ---------------------------------------------------------------------------
// helpers
// ---------------------------------------------------------------------------
__device__ __forceinline__ uint32_t smem_u32(const void* p) {
    uint32_t a;
    asm("{ .reg .u64 t; cvta.to.shared.u64 t, %1; cvt.u32.u64 %0, t; }" : "=r"(a) : "l"(p));
    return a;
}
__device__ __forceinline__ void mmafp(float* c, uint32_t a0, uint32_t a1, uint32_t a2,
                                      uint32_t a3, uint32_t b0, uint32_t b1) {
    asm volatile(
        "mma.sync.aligned.m16n8k16.row.col.f32.f16.f16.f32 "
        "{%0,%1,%2,%3},{%4,%5,%6,%7},{%8,%9},{%0,%1,%2,%3};"
        : "+f"(c[0]), "+f"(c[1]), "+f"(c[2]), "+f"(c[3])
        : "r"(a0), "r"(a1), "r"(a2), "r"(a3), "r"(b0), "r"(b1));
}
__device__ __forceinline__ uint32_t pack2h(float a, float b) {
    __half2 p = __floats2half2_rn(a, b);
    return *(uint32_t*)&p;
}
#define CPA16(d, s) asm volatile("cp.async.cg.shared.global [%0], [%1], 16;" :: "r"(d), "l"(s))
#define CPCOMMIT()  asm volatile("cp.async.commit_group;" ::: "memory")
#define CPWAIT2()   asm volatile("cp.async.wait_group 2;" ::: "memory")

// ---------------------------------------------------------------------------
// Prep: fp32 -> fp16, k-pair permutation within 16-blocks:
// word w: w=2g -> halfs (k=2g,2g+1); w=2g+1 -> (2g+8,2g+9)
// ---------------------------------------------------------------------------
__global__ __launch_bounds__(256) void conv_act(const float* __restrict__ src)
{
    size_t i = (size_t)blockIdx.x * 256 + threadIdx.x;   // one 16-float block
    size_t base = i * 16;
    float f[16];
#pragma unroll
    for (int j = 0; j < 16; j += 4) *(float4*)(f + j) = *(const float4*)(src + base + j);
    uint32_t w[8];
#pragma unroll
    for (int g = 0; g < 4; g++) {
        w[2 * g]     = pack2h(f[2 * g], f[2 * g + 1]);
        w[2 * g + 1] = pack2h(f[2 * g + 8], f[2 * g + 9]);
    }
    *(uint4*)(g_xt + i * 8)     = make_uint4(w[0], w[1], w[2], w[3]);
    *(uint4*)(g_xt + i * 8 + 4) = make_uint4(w[4], w[5], w[6], w[7]);
}

// W [K=2048][N] -> Wt [N][K] fp16, k-pair-permuted; blockIdx.z picks (W0,W1)
__global__ void conv_w2(const float* __restrict__ W0, const float* __restrict__ W1,
                        int N, int wsel0, int wsel1)
{
    __shared__ float t[32][33];
    const float* W = blockIdx.z ? W1 : W0;
    int wsel = blockIdx.z ? wsel1 : wsel0;
    uint32_t* dst = (wsel == 0) ? g_wqt : (wsel == 1) ? g_wkt : (wsel == 2) ? g_wvt : g_wot;
    int n0 = blockIdx.x * 32, k0 = blockIdx.y * 32;
    int tx = threadIdx.x, ty = threadIdx.y;          // (32, 2)
#pragma unroll
    for (int r = ty; r < 32; r += 2)
        t[r][tx] = W[(size_t)(k0 + r) * N + n0 + tx];
    __syncthreads();
    float f[16];
#pragma unroll
    for (int j = 0; j < 16; j++) f[j] = t[ty * 16 + j][tx];
    uint32_t w[8];
#pragma unroll
    for (int g = 0; g < 4; g++) {
        w[2 * g]     = pack2h(f[2 * g], f[2 * g + 1]);
        w[2 * g + 1] = pack2h(f[2 * g + 8], f[2 * g + 9]);
    }
    size_t o = (size_t)(n0 + tx) * (DIM_ / 2) + (size_t)(k0 + ty * 16) / 2;
    *(uint4*)(dst + o)     = make_uint4(w[0], w[1], w[2], w[3]);
    *(uint4*)(dst + o + 4) = make_uint4(w[4], w[5], w[6], w[7]);
}

// ---------------------------------------------------------------------------
// FP16 GEMM, 4-stage cp.async pipeline.
// mode 0: fused QKV — grid.x 0..15 -> Q tile; 16 -> K; 17 -> V.  A = g_xt.
// mode 1: Wo — A = g_at, C = out.
// 128x128 tile, stage = k32, 256 thr (8 warps 2x4, warp 64x32).
// ---------------------------------------------------------------------------
__global__ __launch_bounds__(256, 2) void hgemm(
    int mode, float* __restrict__ pk, float* __restrict__ pv, float* __restrict__ outp)
{
    extern __shared__ uint32_t sm4[];
    const uint32_t* Ag;
    const uint32_t* Bg;
    float* C;
    int N, bn0;
    if (mode == 0) {
        Ag = g_xt;
        if (blockIdx.x < 16)      { Bg = g_wqt; C = g_q; N = DIM_; bn0 = blockIdx.x * 128; }
        else if (blockIdx.x == 16){ Bg = g_wkt; C = pk;  N = HD_;  bn0 = 0; }
        else                      { Bg = g_wvt; C = pv;  N = HD_;  bn0 = 0; }
    } else {
        Ag = g_at; Bg = g_wot; C = outp; N = DIM_; bn0 = blockIdx.x * 128;
    }

    const int KW = DIM_ / 2;   // uint32 words per row
    int tid = threadIdx.x;
    int bm0 = blockIdx.y * 128;
    int warp = tid >> 5, lane = tid & 31;
    int wm = (warp & 1) * 64, wn = (warp >> 1) * 32;
    int lr = lane >> 2, lc = lane & 3;
    uint32_t sbase = smem_u32(sm4);

    float acc[4][4][4];
#pragma unroll
    for (int mt = 0; mt < 4; mt++)
#pragma unroll
        for (int nt = 0; nt < 4; nt++)
#pragma unroll
            for (int i = 0; i < 4; i++) acc[mt][nt][i] = 0.f;

    int c0row = tid >> 2, c0part = tid & 3;
    int c1row = c0row + 64;
    uint32_t d0 = (uint32_t)((((c0part >> 1) * 1024) + c0row * 8 + (c0part & 1) * 4) * 4);
    uint32_t d1 = (uint32_t)((((c0part >> 1) * 1024) + c1row * 8 + (c0part & 1) * 4) * 4);
    int koff = (c0part >> 1) * 8 + (c0part & 1) * 4;
    const uint32_t* a0p = Ag + (size_t)(bm0 + c0row) * KW + koff;
    const uint32_t* a1p = Ag + (size_t)(bm0 + c1row) * KW + koff;
    const uint32_t* b0p = Bg + (size_t)(bn0 + c0row) * KW + koff;
    const uint32_t* b1p = Bg + (size_t)(bn0 + c1row) * KW + koff;

#define ISSUE(st, k0) do { \
        uint32_t sb = sbase + (uint32_t)((st) * 8192); \
        CPA16(sb + d0, a0p + (k0)); \
        CPA16(sb + d1, a1p + (k0)); \
        CPA16(sb + 32768 + d0, b0p + (k0)); \
        CPA16(sb + 32768 + d1, b1p + (k0)); \
        CPCOMMIT(); \
    } while (0)

    ISSUE(0, 0);
    ISSUE(1, 16);
    ISSUE(2, 32);

    const int nk = 64;   // k32 per iter
    for (int t = 0; t < nk; t++) {
        int p = t & 3;
        CPWAIT2();
        __syncthreads();
        if (t + 3 < nk) { ISSUE((t + 3) & 3, (t + 3) * 16); }
        else CPCOMMIT();

#pragma unroll
        for (int kb = 0; kb < 2; kb++) {
            int ab = p * 2048 + kb * 1024;
            int bb = 8192 + p * 2048 + kb * 1024;
            uint2 bfr[4];
#pragma unroll
            for (int nt = 0; nt < 4; nt++)
                bfr[nt] = *(uint2*)&sm4[bb + (wn + nt * 8 + lr) * 8 + lc * 2];
#pragma unroll
            for (int mt = 0; mt < 4; mt++) {
                uint2 alo = *(uint2*)&sm4[ab + (wm + mt * 16 + lr) * 8 + lc * 2];
                uint2 ahi = *(uint2*)&sm4[ab + (wm + mt * 16 + lr + 8) * 8 + lc * 2];
#pragma unroll
                for (int nt = 0; nt < 4; nt++)
                    mmafp(acc[mt][nt], alo.x, ahi.x, alo.y, ahi.y, bfr[nt].x, bfr[nt].y);
            }
        }
    }

#pragma unroll
    for (int mt = 0; mt < 4; mt++) {
        int row = bm0 + wm + mt * 16 + lr;
#pragma unroll
        for (int nt = 0; nt < 4; nt++) {
            int col = bn0 + wn + nt * 8 + lc * 2;
            *(float2*)&C[(size_t)row * N + col]       = make_float2(acc[mt][nt][0], acc[mt][nt][1]);
            *(float2*)&C[(size_t)(row + 8) * N + col] = make_float2(acc[mt][nt][2], acc[mt][nt][3]);
        }
    }
#undef ISSUE
}

// ---------------------------------------------------------------------------
// RoPE + conversion kernels
// ---------------------------------------------------------------------------
__global__ __launch_bounds__(256) void rope_q_split()
{
    int idx = blockIdx.x * 256 + threadIdx.x;
    int j = idx & 63;
    int h = (idx >> 6) & (H_ - 1);
    int t = (idx >> 10) & (T_ - 1);
    int b = idx >> 21;
    const float scale = 0.08838834764831845f;
    float inv = powf(10000.0f, -(float)j * (1.0f / 64.0f));
    float ang = (float)t * inv;
    float sv, cv;
    sincosf(ang, &sv, &cv);
    size_t base = (((size_t)b * T_ + t) * H_ + h) * (size_t)HD_;
    float x1 = g_q[base + j], x2 = g_q[base + j + 64];
    g_qh[base + j]      = __float2half((x1 * cv - x2 * sv) * scale);
    g_qh[base + j + 64] = __float2half((x2 * cv + x1 * sv) * scale);
}

__global__ __launch_bounds__(256) void rope_k_split(float* __restrict__ kb)
{
    int idx = blockIdx.x * 256 + threadIdx.x;
    int j = idx & 63;
    int t = (idx >> 6) & (T_ - 1);
    int b = idx >> 17;
    float inv = powf(10000.0f, -(float)j * (1.0f / 64.0f));
    float ang = (float)t * inv;
    float sv, cv;
    sincosf(ang, &sv, &cv);
    size_t base = ((size_t)b * T_ + t) * (size_t)HD_;
    float x1 = kb[base + j], x2 = kb[base + j + 64];
    float r1 = x1 * cv - x2 * sv;
    float r2 = x2 * cv + x1 * sv;
    kb[base + j] = r1;              // present_k output (fp32)
    kb[base + j + 64] = r2;
    g_kh[base + j]      = __float2half(r1);
    g_kh[base + j + 64] = __float2half(r2);
}

// V: [B,T,HD] fp32 -> [B,HD,T] fp16 hi/lo (transpose + split)
__global__ void v_split_t(const float* __restrict__ vb)
{
    __shared__ float tile[32][33];
    int t0 = blockIdx.x * 32, d0 = blockIdx.y * 32, b = blockIdx.z;
    int tx = threadIdx.x, ty = threadIdx.y;
#pragma unroll
    for (int r = ty; r < 32; r += 8)
        tile[r][tx] = vb[((size_t)b * T_ + t0 + r) * HD_ + d0 + tx];
    __syncthreads();
#pragma unroll
    for (int r = ty; r < 32; r += 8) {
        float v = tile[tx][r];
        __half hh = __float2half(v);
        size_t o = ((size_t)b * HD_ + d0 + r) * T_ + t0 + tx;
        g_vth[o] = hh;
        g_vtl[o] = __float2half(v - __half2float(hh));
    }
}

// ---------------------------------------------------------------------------
// Flash attention: S = fp16 x1, PV = fp16 x2 (V hi/lo). BQ=BKV=64, 128 thr.
// Output written directly as k-pair-permuted fp16 into g_at (Wo A-operand).
// ---------------------------------------------------------------------------
#define FBQ 64
#define FBKV 64
#define KSTR 136
#define VSTR 72

__global__ __launch_bounds__(128, 2) void flash_mixed()
{
    extern __shared__ __half smh[];
    __half* Kh  = smh;                      // [64][KSTR]
    __half* VTh = Kh + 64 * KSTR;           // [128][VSTR]
    __half* VTl = VTh + 128 * VSTR;
    __half* Ph  = VTl + 128 * VSTR;         // [64][VSTR]

    int tid = threadIdx.x;
    int w = tid >> 5, lane = tid & 31;
    int lr = lane >> 2, lc = lane & 3;
    int qb = blockIdx.x;
    int bh = (int)blockIdx.y;
    int b = bh >> 4, h = bh & 15;
    int q0 = qb * FBQ;
    int rb = w * 16;

    // Q fragments (fp16) in registers
    uint32_t qf[8][4];
    {
        const __half* qh = g_qh + (((size_t)b * T_ + q0) * H_ + h) * (size_t)HD_;
#pragma unroll
        for (int kk = 0; kk < 8; kk++) {
            int ke = kk * 16;
            qf[kk][0] = *(const uint32_t*)&qh[(size_t)(rb + lr) * DIM_ + ke + 2 * lc];
            qf[kk][1] = *(const uint32_t*)&qh[(size_t)(rb + lr + 8) * DIM_ + ke + 2 * lc];
            qf[kk][2] = *(const uint32_t*)&qh[(size_t)(rb + lr) * DIM_ + ke + 2 * lc + 8];
            qf[kk][3] = *(const uint32_t*)&qh[(size_t)(rb + lr + 8) * DIM_ + ke + 2 * lc + 8];
        }
    }

    float m0r = -1e30f, m1r = -1e30f, l0r = 0.f, l1r = 0.f;
    float O[16][4];
#pragma unroll
    for (int i = 0; i < 16; i++)
#pragma unroll
        for (int j = 0; j < 4; j++) O[i][j] = 0.f;

    const __half* kbh = g_kh + (size_t)b * T_ * HD_;
    const __half* vbh = g_vth + (size_t)b * HD_ * T_;
    const __half* vbl = g_vtl + (size_t)b * HD_ * T_;

    for (int kt = 0; kt <= qb; kt++) {
        int k0 = kt * FBKV;
        __syncthreads();

        // K tile: 64 x 128 fp16
#pragma unroll
        for (int it = 0; it < 8; it++) {
            int i = tid + it * 128;
            int r = i >> 4, c = (i & 15) * 8;
            *(uint4*)&Kh[r * KSTR + c] = *(const uint4*)&kbh[(size_t)(k0 + r) * HD_ + c];
        }
        // V^T tile: 128 x 64 fp16 hi+lo
#pragma unroll
        for (int it = 0; it < 8; it++) {
            int i = tid + it * 128;
            int r = i >> 3, c = (i & 7) * 8;
            size_t ga = (size_t)r * T_ + k0 + c;
            *(uint4*)&VTh[r * VSTR + c] = *(const uint4*)&vbh[ga];
            *(uint4*)&VTl[r * VSTR + c] = *(const uint4*)&vbl[ga];
        }
        __syncthreads();

        // S = Q @ K^T (fp16 x1)
        float sacc[8][4];
#pragma unroll
        for (int nt = 0; nt < 8; nt++)
#pragma unroll
            for (int j = 0; j < 4; j++) sacc[nt][j] = 0.f;

#pragma unroll
        for (int kk = 0; kk < 8; kk++) {
            int ke = kk * 16;
#pragma unroll
            for (int nt = 0; nt < 8; nt++) {
                int n = nt * 8 + lr;
                uint32_t b0 = *(uint32_t*)&Kh[n * KSTR + ke + 2 * lc];
                uint32_t b1 = *(uint32_t*)&Kh[n * KSTR + ke + 2 * lc + 8];
                mmafp(sacc[nt], qf[kk][0], qf[kk][1], qf[kk][2], qf[kk][3], b0, b1);
            }
        }

        if (kt == qb) {
            int r0g = rb + lr, r1g = r0g + 8;
#pragma unroll
            for (int nt = 0; nt < 8; nt++) {
                int cg = nt * 8 + 2 * lc;
                if (cg > r0g)     sacc[nt][0] = -1e30f;
                if (cg + 1 > r0g) sacc[nt][1] = -1e30f;
                if (cg > r1g)     sacc[nt][2] = -1e30f;
                if (cg + 1 > r1g) sacc[nt][3] = -1e30f;
            }
        }

        float mt0 = -1e30f, mt1 = -1e30f;
#pragma unroll
        for (int nt = 0; nt < 8; nt++) {
            mt0 = fmaxf(mt0, fmaxf(sacc[nt][0], sacc[nt][1]));
            mt1 = fmaxf(mt1, fmaxf(sacc[nt][2], sacc[nt][3]));
        }
        mt0 = fmaxf(mt0, __shfl_xor_sync(0xffffffff, mt0, 1));
        mt0 = fmaxf(mt0, __shfl_xor_sync(0xffffffff, mt0, 2));
        mt1 = fmaxf(mt1, __shfl_xor_sync(0xffffffff, mt1, 1));
        mt1 = fmaxf(mt1, __shfl_xor_sync(0xffffffff, mt1, 2));

        float mn0 = fmaxf(m0r, mt0), mn1 = fmaxf(m1r, mt1);
        float al0f = __expf(m0r - mn0), al1f = __expf(m1r - mn1);
        m0r = mn0; m1r = mn1;

        float rs0 = 0.f, rs1 = 0.f;
#pragma unroll
        for (int nt = 0; nt < 8; nt++) {
            float p0 = __expf(sacc[nt][0] - mn0);
            float p1 = __expf(sacc[nt][1] - mn0);
            float p2 = __expf(sacc[nt][2] - mn1);
            float p3 = __expf(sacc[nt][3] - mn1);
            rs0 += p0 + p1; rs1 += p2 + p3;
            *(uint32_t*)&Ph[(rb + lr) * VSTR + nt * 8 + 2 * lc]     = pack2h(p0, p1);
            *(uint32_t*)&Ph[(rb + lr + 8) * VSTR + nt * 8 + 2 * lc] = pack2h(p2, p3);
        }
        rs0 += __shfl_xor_sync(0xffffffff, rs0, 1);
        rs0 += __shfl_xor_sync(0xffffffff, rs0, 2);
        rs1 += __shfl_xor_sync(0xffffffff, rs1, 1);
        rs1 += __shfl_xor_sync(0xffffffff, rs1, 2);
        l0r = l0r * al0f + rs0;
        l1r = l1r * al1f + rs1;

#pragma unroll
        for (int nt = 0; nt < 16; nt++) {
            O[nt][0] *= al0f; O[nt][1] *= al0f;
            O[nt][2] *= al1f; O[nt][3] *= al1f;
        }
        __syncwarp();

        // O += P @ V (fp16 x2: V hi + V lo)
#pragma unroll
        for (int kk = 0; kk < 4; kk++) {
            int ke = kk * 16;
            uint32_t a0 = *(uint32_t*)&Ph[(rb + lr) * VSTR + ke + 2 * lc];
            uint32_t a1 = *(uint32_t*)&Ph[(rb + lr + 8) * VSTR + ke + 2 * lc];
            uint32_t a2 = *(uint32_t*)&Ph[(rb + lr) * VSTR + ke + 2 * lc + 8];
            uint32_t a3 = *(uint32_t*)&Ph[(rb + lr + 8) * VSTR + ke + 2 * lc + 8];
#pragma unroll
            for (int nt = 0; nt < 16; nt++) {
                int n = nt * 8 + lr;
                uint32_t bh0 = *(uint32_t*)&VTh[n * VSTR + ke + 2 * lc];
                uint32_t bh1 = *(uint32_t*)&VTh[n * VSTR + ke + 2 * lc + 8];
                uint32_t bl0 = *(uint32_t*)&VTl[n * VSTR + ke + 2 * lc];
                uint32_t bl1 = *(uint32_t*)&VTl[n * VSTR + ke + 2 * lc + 8];
                mmafp(O[nt], a0, a1, a2, a3, bh0, bh1);
                mmafp(O[nt], a0, a1, a2, a3, bl0, bl1);
            }
        }
    }

    // finalize: write k-pair-permuted fp16 directly into g_at [row][word]
    // col = h*128 + nt*8 + 2*lc ; word = (h*8 + nt/2)*8 + 2*lc + (nt&1)
    float inv0 = 1.f / l0r, inv1 = 1.f / l1r;
    uint32_t* oa = g_at + (size_t)(b * T_ + q0) * (DIM_ / 2);
#pragma unroll
    for (int nt = 0; nt < 16; nt++) {
        int word = (h * 8 + (nt >> 1)) * 8 + 2 * lc + (nt & 1);
        oa[(size_t)(rb + lr) * (DIM_ / 2) + word]     = pack2h(O[nt][0] * inv0, O[nt][1] * inv0);
        oa[(size_t)(rb + lr + 8) * (DIM_ / 2) + word] = pack2h(O[nt][2] * inv1, O[nt][3] * inv1);
    }
}

static const int FLASH_SMEM = (64 * KSTR + 2 * 128 * VSTR + 64 * VSTR) * 2;
static const int GEMM_SMEM = 65536;

// ---------------------------------------------------------------------------
extern "C" void kernel_launch(void* const* d_in, const int* in_sizes, int n_in,
                              void* d_out, int out_size)
{
    const float* x  = (const float*)d_in[0];
    const float* Wq = (const float*)d_in[1];
    const float* Wk = (const float*)d_in[2];
    const float* Wv = (const float*)d_in[3];
    const float* Wo = (const float*)d_in[4];

    float* out = (float*)d_out;                       // [B,T,DIM]
    float* pk  = out + (size_t)BT_ * DIM_;            // present_k [B,1,T,HD]
    float* pv  = pk + (size_t)BT_ * HD_;              // present_v [B,1,T,HD]

    cudaFuncSetAttribute(flash_mixed, cudaFuncAttributeMaxDynamicSharedMemorySize, FLASH_SMEM);
    cudaFuncSetAttribute(hgemm, cudaFuncAttributeMaxDynamicSharedMemorySize, GEMM_SMEM);

    // prep: fp16 conversions (3 launches)
    conv_act<<<(BT_ * DIM_ / 16) / 256, 256>>>(x);
    conv_w2<<<dim3(DIM_ / 32, DIM_ / 32, 2), dim3(32, 2)>>>(Wq, Wo, DIM_, 0, 3);
    conv_w2<<<dim3(HD_ / 32, DIM_ / 32, 2), dim3(32, 2)>>>(Wk, Wv, HD_, 1, 2);

    // fused Q/K/V projection: x tiles 0..15 = Q, 16 = K, 17 = V
    hgemm<<<dim3(18, BT_ / 128), 256, GEMM_SMEM>>>(0, pk, pv, nullptr);

    // RoPE + fp16 conversion (+ V transpose/split)
    rope_q_split<<<(BT_ * H_ * 64) / 256, 256>>>();
    rope_k_split<<<(BT_ * 64) / 256, 256>>>(pk);
    v_split_t<<<dim3(T_ / 32, HD_ / 32, B_), dim3(32, 8)>>>(pv);

    // Attention -> g_at (fp16, permuted; Wo A-operand)
    flash_mixed<<<dim3(T_ / FBQ, B_ * H_), 128, FLASH_SMEM>>>();

    // out = attn @ Wo
    hgemm<<<dim3(16, BT_ / 128), 256, GEMM_SMEM>>>(1, nullptr, nullptr, out);
}